// round 14
// baseline (speedup 1.0000x reference)
#include <cuda_runtime.h>
#include <math.h>

#define EMB 1024
#define HID 1024
#define SEQ 2048
#define NEMO 16
#define LABELS 7
#define G4 (4*HID)

#define NB 128        // blocks in sequential kernel (<= 148 SMs -> co-resident)
#define JPB (HID/NB)  // 8 hidden units per block
#define TPB 256

// ---------------- static device scratch (no allocations allowed) ----------------
// SeqState / k_seq / k_init keep the R5 protocol VERBATIM (it passed twice);
// the ONLY k_seq change vs R12 is MUFU-based activations (serial-path math,
// not synchronization). Every sync-protocol variant starved on HW; do not touch.
struct SeqState {
    unsigned counter;
    unsigned pad[31];
    float h[2][HID];     // double-buffered hidden state
};

__device__ float g_C [SEQ * EMB];       // relu(comb) per step       (8 MB)
__device__ float g_G [SEQ * G4];        // W_ih @ C + b_ih + b_hh    (32 MB)
__device__ float g_emoji[EMB];
__device__ float g_const2[EMB];         // We @ emoji_ave + comb_b
__device__ SeqState g_st;

// ---------------- small kernels ----------------
__global__ void k_init() {
    if (threadIdx.x == 0) g_st.counter = 0u;
    float* h = &g_st.h[0][0];
    for (int i = threadIdx.x; i < 2 * HID; i += blockDim.x) h[i] = 0.f;
}

__global__ void k_emoji(const int* __restrict__ eids, const float* __restrict__ eemb) {
    int e = blockIdx.x * blockDim.x + threadIdx.x;
    if (e < EMB) {
        float s = 0.f;
        #pragma unroll
        for (int n = 0; n < NEMO; n++)
            s += eemb[(size_t)eids[n] * EMB + e];
        g_emoji[e] = s * (1.0f / NEMO);
    }
}

// const2[i] = dot(comb_W[i, EMB:2*EMB], emoji_ave) + comb_b[i]; warp per row
__global__ void k_const2(const float* __restrict__ combW, const float* __restrict__ combB) {
    int warp = threadIdx.x >> 5, lane = threadIdx.x & 31;
    int row = blockIdx.x * 8 + warp;
    const float* wr = combW + (size_t)row * (2 * EMB) + EMB;
    float s = 0.f;
    for (int k = lane; k < EMB; k += 32) s += wr[k] * g_emoji[k];
    #pragma unroll
    for (int off = 16; off; off >>= 1) s += __shfl_xor_sync(0xffffffffu, s, off);
    if (lane == 0) g_const2[row] = s + combB[row];
}

// ---------------- SIMT SGEMM:  C[M,N] = A[M,K] @ B[N,K]^T + bias(+bias2) (opt relu) ----
// 128x128 tile, TK=16, 256 threads, 8x8 per thread, double-buffered smem.
// If ids != nullptr, A row m is A[ids[m]] (fused embedding gather).
// bias2 (optional) folds a second bias vector into the epilogue (kills k_bsum).
__global__ __launch_bounds__(256) void sgemm_nt(
    const float* __restrict__ A, int lda, const int* __restrict__ ids,
    const float* __restrict__ B, int ldb,
    const float* __restrict__ bias, const float* __restrict__ bias2,
    float* __restrict__ Cc, int ldc,
    int K, int relu)
{
    __shared__ float As[2][16][128];
    __shared__ float Bs[2][16][128];

    const int tid = threadIdx.x;
    const int m0 = blockIdx.y * 128;
    const int n0 = blockIdx.x * 128;
    const int tx = tid & 15;    // n micro-tile index
    const int ty = tid >> 4;    // m micro-tile index
    const int lr = tid >> 2;    // 0..63: tile row for loads
    const int lq = tid & 3;     // k-quad for loads

    const float* aptr[2];
    const float* bptr[2];
    #pragma unroll
    for (int s = 0; s < 2; s++) {
        int r = lr + s * 64;
        int am = ids ? ids[m0 + r] : (m0 + r);
        aptr[s] = A + (size_t)am * lda + lq * 4;
        bptr[s] = B + (size_t)(n0 + r) * ldb + lq * 4;
    }

    float4 ra[2], rb[2];

    float acc[8][8];
    #pragma unroll
    for (int r = 0; r < 8; r++)
        #pragma unroll
        for (int c = 0; c < 8; c++) acc[r][c] = 0.f;

    // prologue: tile 0 -> buf 0
    #pragma unroll
    for (int s = 0; s < 2; s++) { ra[s] = *(const float4*)(aptr[s]); rb[s] = *(const float4*)(bptr[s]); }
    #pragma unroll
    for (int s = 0; s < 2; s++) {
        int r = lr + s * 64;
        As[0][lq*4+0][r] = ra[s].x; As[0][lq*4+1][r] = ra[s].y;
        As[0][lq*4+2][r] = ra[s].z; As[0][lq*4+3][r] = ra[s].w;
        Bs[0][lq*4+0][r] = rb[s].x; Bs[0][lq*4+1][r] = rb[s].y;
        Bs[0][lq*4+2][r] = rb[s].z; Bs[0][lq*4+3][r] = rb[s].w;
    }
    __syncthreads();

    int buf = 0;
    for (int k0 = 16; k0 <= K; k0 += 16) {
        if (k0 < K) {
            #pragma unroll
            for (int s = 0; s < 2; s++) {
                ra[s] = *(const float4*)(aptr[s] + k0);
                rb[s] = *(const float4*)(bptr[s] + k0);
            }
        }

        #pragma unroll
        for (int k = 0; k < 16; k++) {
            float4 a0 = *(const float4*)&As[buf][k][ty * 8];
            float4 a1 = *(const float4*)&As[buf][k][ty * 8 + 4];
            float4 b0 = *(const float4*)&Bs[buf][k][tx * 8];
            float4 b1 = *(const float4*)&Bs[buf][k][tx * 8 + 4];
            float a[8] = {a0.x, a0.y, a0.z, a0.w, a1.x, a1.y, a1.z, a1.w};
            float b[8] = {b0.x, b0.y, b0.z, b0.w, b1.x, b1.y, b1.z, b1.w};
            #pragma unroll
            for (int r = 0; r < 8; r++)
                #pragma unroll
                for (int c = 0; c < 8; c++)
                    acc[r][c] += a[r] * b[c];
        }

        if (k0 < K) {
            int nb = buf ^ 1;
            #pragma unroll
            for (int s = 0; s < 2; s++) {
                int r = lr + s * 64;
                As[nb][lq*4+0][r] = ra[s].x; As[nb][lq*4+1][r] = ra[s].y;
                As[nb][lq*4+2][r] = ra[s].z; As[nb][lq*4+3][r] = ra[s].w;
                Bs[nb][lq*4+0][r] = rb[s].x; Bs[nb][lq*4+1][r] = rb[s].y;
                Bs[nb][lq*4+2][r] = rb[s].z; Bs[nb][lq*4+3][r] = rb[s].w;
            }
            __syncthreads();
            buf = nb;
        }
    }

    #pragma unroll
    for (int r = 0; r < 8; r++) {
        int m = m0 + ty * 8 + r;
        float* cp = Cc + (size_t)m * ldc + n0 + tx * 8;
        #pragma unroll
        for (int c = 0; c < 8; c++) {
            int n = n0 + tx * 8 + c;
            float v = acc[r][c] + bias[n];
            if (bias2) v += bias2[n];
            if (relu) v = fmaxf(v, 0.f);
            cp[c] = v;
        }
    }
}

// ---------------- persistent sequential LSTM kernel (R5 protocol, fast activations) ----
// 128 blocks x 256 threads. Block b owns hidden units j in [b*8, b*8+8):
// 32 rows of W_hh (4 gates x 8 units) register-resident (128 floats/thread).
// One grid barrier per step (double-buffered h). Sync protocol byte-identical
// to the twice-proven R5 version; ONLY the activation math changed (MUFU EX2
// based sigmoid/tanh; pre-activations are ~0.02-scale and c-dynamics are
// contractive, so the ~1e-6 per-step perturbation stays ~1e-5 at the output).
__global__ __launch_bounds__(TPB, 1) void k_seq(const float* __restrict__ Whh,
                                                const float* __restrict__ G)
{
    const int b = blockIdx.x;
    const int tid = threadIdx.x;
    const int warp = tid >> 5, lane = tid & 31;

    __shared__ float hsh[HID];
    __shared__ float gsum[32];
    __shared__ float csh[JPB];
    if (tid < JPB) csh[tid] = 0.f;

    // rows: local row lr = warp*4+rr; gate = lr>>3; jloc = lr&7; row = gate*1024 + b*8 + jloc
    int rows[4];
    float w[4][32];
    #pragma unroll
    for (int rr = 0; rr < 4; rr++) {
        int lr = warp * 4 + rr;
        int gate = lr >> 3, jloc = lr & 7;
        rows[rr] = (gate << 10) + b * JPB + jloc;
        const float* wrow = Whh + (size_t)rows[rr] * HID + lane;
        #pragma unroll
        for (int i = 0; i < 32; i++) w[rr][i] = wrow[i * 32];
    }

    for (int t = 0; t < SEQ; t++) {
        // prefetch precomputed gate terms for this step (independent of h)
        float g0 = 0.f, g1 = 0.f, g2 = 0.f, g3 = 0.f;
        if (lane == 0) {
            const float* gt = G + (size_t)t * G4;
            g0 = __ldcg(gt + rows[0]);
            g1 = __ldcg(gt + rows[1]);
            g2 = __ldcg(gt + rows[2]);
            g3 = __ldcg(gt + rows[3]);
        }

        // load h (written by other blocks last step) — bypass L1
        const float* hg = g_st.h[t & 1];
        #pragma unroll
        for (int i = 0; i < HID / TPB; i++)
            hsh[tid + i * TPB] = __ldcg(hg + tid + i * TPB);
        __syncthreads();

        float hreg[32];
        #pragma unroll
        for (int i = 0; i < 32; i++) hreg[i] = hsh[i * 32 + lane];

        float a0 = 0.f, a1 = 0.f, a2 = 0.f, a3 = 0.f;
        #pragma unroll
        for (int i = 0; i < 32; i++) {
            a0 += w[0][i] * hreg[i];
            a1 += w[1][i] * hreg[i];
            a2 += w[2][i] * hreg[i];
            a3 += w[3][i] * hreg[i];
        }
        #pragma unroll
        for (int off = 16; off; off >>= 1) {
            a0 += __shfl_xor_sync(0xffffffffu, a0, off);
            a1 += __shfl_xor_sync(0xffffffffu, a1, off);
            a2 += __shfl_xor_sync(0xffffffffu, a2, off);
            a3 += __shfl_xor_sync(0xffffffffu, a3, off);
        }
        if (lane == 0) {
            gsum[warp * 4 + 0] = a0 + g0;
            gsum[warp * 4 + 1] = a1 + g1;
            gsum[warp * 4 + 2] = a2 + g2;
            gsum[warp * 4 + 3] = a3 + g3;
        }
        __syncthreads();

        if (tid < JPB) {
            float iv = gsum[tid];            // gate 0: input
            float fv = gsum[8 + tid];        // gate 1: forget
            float gv = gsum[16 + tid];       // gate 2: cell
            float ov = gsum[24 + tid];       // gate 3: output
            // MUFU-based activations (critical-path latency cut ~5x vs libm)
            float is = 1.f / (1.f + __expf(-iv));
            float fs = 1.f / (1.f + __expf(-fv));
            float os = 1.f / (1.f + __expf(-ov));
            float tg = 1.f - 2.f / (__expf(2.f * gv) + 1.f);   // tanh(gv)
            float cn = fs * csh[tid] + is * tg;
            csh[tid] = cn;
            float tc = 1.f - 2.f / (__expf(2.f * cn) + 1.f);   // tanh(cn)
            float hn = os * tc;
            g_st.h[(t + 1) & 1][b * JPB + tid] = hn;
        }
        __syncthreads();

        // grid barrier (release h-writes, acquire others') — VERBATIM R5
        if (tid == 0) {
            __threadfence();
            atomicAdd(&g_st.counter, 1u);
            unsigned target = (unsigned)(t + 1) * NB;
            while (*((volatile unsigned*)&g_st.counter) < target) { }
            __threadfence();
        }
        __syncthreads();
    }
}

// out[l] = dot(out_W[l], h_final) + out_b[l]; final h lives in buffer 0 (SEQ even)
__global__ void k_out(const float* __restrict__ outW, const float* __restrict__ outB,
                      float* __restrict__ out)
{
    int warp = threadIdx.x >> 5, lane = threadIdx.x & 31;
    if (warp < LABELS) {
        const float* wr = outW + (size_t)warp * HID;
        const float* h = g_st.h[0];
        float s = 0.f;
        for (int k = lane; k < HID; k += 32) s += wr[k] * h[k];
        #pragma unroll
        for (int off = 16; off; off >>= 1) s += __shfl_xor_sync(0xffffffffu, s, off);
        if (lane == 0) out[warp] = s + outB[warp];
    }
}

// ---------------- launch ----------------
extern "C" void kernel_launch(void* const* d_in, const int* in_sizes, int n_in,
                              void* d_out, int out_size)
{
    const int*   sids  = (const int*)  d_in[0];
    const int*   eids  = (const int*)  d_in[1];
    const float* wemb  = (const float*)d_in[2];
    const float* eemb  = (const float*)d_in[3];
    // d_in[4] attn_W, d_in[5] attn_b: mathematically dead (softmax of 1 logit == 1)
    const float* combW = (const float*)d_in[6];
    const float* combB = (const float*)d_in[7];
    const float* Wih   = (const float*)d_in[8];
    const float* Whh   = (const float*)d_in[9];
    const float* bih   = (const float*)d_in[10];
    const float* bhh   = (const float*)d_in[11];
    const float* outW  = (const float*)d_in[12];
    const float* outB  = (const float*)d_in[13];
    float* out = (float*)d_out;

    void *pC = 0, *pG = 0, *pc2 = 0;
    cudaGetSymbolAddress(&pC,  g_C);
    cudaGetSymbolAddress(&pG,  g_G);
    cudaGetSymbolAddress(&pc2, g_const2);

    k_init  <<<1, 256>>>();
    k_emoji <<<(EMB + 255) / 256, 256>>>(eids, eemb);
    k_const2<<<EMB / 8, 256>>>(combW, combB);

    // C = relu(gather(word_emb, sids) @ Wx^T + const2), Wx = comb_W[:, 0:EMB]
    dim3 gridC(EMB / 128, SEQ / 128);
    sgemm_nt<<<gridC, 256>>>(wemb, EMB, sids, combW, 2 * EMB,
                             (const float*)pc2, (const float*)0,
                             (float*)pC, EMB, EMB, 1);

    // G = C @ W_ih^T + b_ih + b_hh   (both biases folded into epilogue)
    dim3 gridG(G4 / 128, SEQ / 128);
    sgemm_nt<<<gridG, 256>>>((const float*)pC, EMB, (const int*)0, Wih, EMB,
                             bih, bhh, (float*)pG, G4, EMB, 0);

    k_seq<<<NB, TPB>>>(Whh, (const float*)pG);
    k_out<<<1, 256>>>(outW, outB, out);
}

// round 15
// speedup vs baseline: 1.0314x; 1.0314x over previous
#include <cuda_runtime.h>
#include <math.h>

#define EMB 1024
#define HID 1024
#define SEQ 2048
#define NEMO 16
#define LABELS 7
#define G4 (4*HID)

#define NB 128        // blocks in sequential kernel (<= 148 SMs -> co-resident)
#define JPB (HID/NB)  // 8 hidden units per block (= warps per block)
#define TPB 256

// ---------------- static device scratch (no allocations allowed) ----------------
// Grid-barrier protocol (fence + atomic + volatile spin + fence) is VERBATIM
// from the R5 kernel (passed 3x). Every protocol variant starved on HW; do not touch.
struct SeqState {
    unsigned counter;
    unsigned pad[31];
    float h[2][HID];     // double-buffered hidden state
};

__device__ float g_C [SEQ * EMB];       // relu(comb) per step       (8 MB)
__device__ float g_G [SEQ * G4];        // W_ih @ C + b_ih + b_hh    (32 MB)
__device__ float g_const2[EMB];         // We @ emoji_ave + comb_b
__device__ SeqState g_st;

// ---------------- fused prep kernel (launch #1) ----------------
// 128 blocks x 256 threads. Every block: emoji_ave -> smem, then const2 for
// its 8 comb_W rows (warp per row). Block 0 additionally zeroes the barrier
// counter and both h buffers (k_seq comes later in stream order).
__global__ __launch_bounds__(TPB) void k_prep(const int* __restrict__ eids,
                                              const float* __restrict__ eemb,
                                              const float* __restrict__ combW,
                                              const float* __restrict__ combB)
{
    __shared__ float esh[EMB];
    const int tid = threadIdx.x;
    const int warp = tid >> 5, lane = tid & 31;

    // emoji_ave into smem (redundant per block; tiny, L2-cached)
    for (int e = tid; e < EMB; e += TPB) {
        float s = 0.f;
        #pragma unroll
        for (int n = 0; n < NEMO; n++)
            s += eemb[(size_t)eids[n] * EMB + e];
        esh[e] = s * (1.0f / NEMO);
    }

    if (blockIdx.x == 0) {
        if (tid == 0) g_st.counter = 0u;
        float* h = &g_st.h[0][0];
        for (int i = tid; i < 2 * HID; i += TPB) h[i] = 0.f;
    }
    __syncthreads();

    // const2[row] = dot(comb_W[row, EMB:2EMB], emoji_ave) + comb_b[row]
    int row = blockIdx.x * 8 + warp;
    const float* wr = combW + (size_t)row * (2 * EMB) + EMB;
    float s = 0.f;
    for (int k = lane; k < EMB; k += 32) s += wr[k] * esh[k];
    #pragma unroll
    for (int off = 16; off; off >>= 1) s += __shfl_xor_sync(0xffffffffu, s, off);
    if (lane == 0) g_const2[row] = s + combB[row];
}

// ---------------- SIMT SGEMM:  C[M,N] = A[M,K] @ B[N,K]^T + bias(+bias2) (opt relu) ----
// 128x128 tile, TK=16, 256 threads, 8x8 per thread, double-buffered smem.
// If ids != nullptr, A row m is A[ids[m]] (fused embedding gather).
__global__ __launch_bounds__(256) void sgemm_nt(
    const float* __restrict__ A, int lda, const int* __restrict__ ids,
    const float* __restrict__ B, int ldb,
    const float* __restrict__ bias, const float* __restrict__ bias2,
    float* __restrict__ Cc, int ldc,
    int K, int relu)
{
    __shared__ float As[2][16][128];
    __shared__ float Bs[2][16][128];

    const int tid = threadIdx.x;
    const int m0 = blockIdx.y * 128;
    const int n0 = blockIdx.x * 128;
    const int tx = tid & 15;    // n micro-tile index
    const int ty = tid >> 4;    // m micro-tile index
    const int lr = tid >> 2;    // 0..63: tile row for loads
    const int lq = tid & 3;     // k-quad for loads

    const float* aptr[2];
    const float* bptr[2];
    #pragma unroll
    for (int s = 0; s < 2; s++) {
        int r = lr + s * 64;
        int am = ids ? ids[m0 + r] : (m0 + r);
        aptr[s] = A + (size_t)am * lda + lq * 4;
        bptr[s] = B + (size_t)(n0 + r) * ldb + lq * 4;
    }

    float4 ra[2], rb[2];

    float acc[8][8];
    #pragma unroll
    for (int r = 0; r < 8; r++)
        #pragma unroll
        for (int c = 0; c < 8; c++) acc[r][c] = 0.f;

    // prologue: tile 0 -> buf 0
    #pragma unroll
    for (int s = 0; s < 2; s++) { ra[s] = *(const float4*)(aptr[s]); rb[s] = *(const float4*)(bptr[s]); }
    #pragma unroll
    for (int s = 0; s < 2; s++) {
        int r = lr + s * 64;
        As[0][lq*4+0][r] = ra[s].x; As[0][lq*4+1][r] = ra[s].y;
        As[0][lq*4+2][r] = ra[s].z; As[0][lq*4+3][r] = ra[s].w;
        Bs[0][lq*4+0][r] = rb[s].x; Bs[0][lq*4+1][r] = rb[s].y;
        Bs[0][lq*4+2][r] = rb[s].z; Bs[0][lq*4+3][r] = rb[s].w;
    }
    __syncthreads();

    int buf = 0;
    for (int k0 = 16; k0 <= K; k0 += 16) {
        if (k0 < K) {
            #pragma unroll
            for (int s = 0; s < 2; s++) {
                ra[s] = *(const float4*)(aptr[s] + k0);
                rb[s] = *(const float4*)(bptr[s] + k0);
            }
        }

        #pragma unroll
        for (int k = 0; k < 16; k++) {
            float4 a0 = *(const float4*)&As[buf][k][ty * 8];
            float4 a1 = *(const float4*)&As[buf][k][ty * 8 + 4];
            float4 b0 = *(const float4*)&Bs[buf][k][tx * 8];
            float4 b1 = *(const float4*)&Bs[buf][k][tx * 8 + 4];
            float a[8] = {a0.x, a0.y, a0.z, a0.w, a1.x, a1.y, a1.z, a1.w};
            float b[8] = {b0.x, b0.y, b0.z, b0.w, b1.x, b1.y, b1.z, b1.w};
            #pragma unroll
            for (int r = 0; r < 8; r++)
                #pragma unroll
                for (int c = 0; c < 8; c++)
                    acc[r][c] += a[r] * b[c];
        }

        if (k0 < K) {
            int nb = buf ^ 1;
            #pragma unroll
            for (int s = 0; s < 2; s++) {
                int r = lr + s * 64;
                As[nb][lq*4+0][r] = ra[s].x; As[nb][lq*4+1][r] = ra[s].y;
                As[nb][lq*4+2][r] = ra[s].z; As[nb][lq*4+3][r] = ra[s].w;
                Bs[nb][lq*4+0][r] = rb[s].x; Bs[nb][lq*4+1][r] = rb[s].y;
                Bs[nb][lq*4+2][r] = rb[s].z; Bs[nb][lq*4+3][r] = rb[s].w;
            }
            __syncthreads();
            buf = nb;
        }
    }

    #pragma unroll
    for (int r = 0; r < 8; r++) {
        int m = m0 + ty * 8 + r;
        float* cp = Cc + (size_t)m * ldc + n0 + tx * 8;
        #pragma unroll
        for (int c = 0; c < 8; c++) {
            int n = n0 + tx * 8 + c;
            float v = acc[r][c] + bias[n];
            if (bias2) v += bias2[n];
            if (relu) v = fmaxf(v, 0.f);
            cp[c] = v;
        }
    }
}

// ---------------- persistent sequential LSTM kernel ----------------
// 128 blocks x 256 threads (8 warps). WARP-PER-UNIT layout: warp w owns ALL
// FOUR gate rows of hidden unit u = b*8+w (128 W_hh floats/thread, register-
// resident). After the intra-warp shfl reduce, lane 0 holds i,f,g,o for its
// unit: activations + h-store happen immediately — no gsum smem exchange, one
// fewer __syncthreads on the serial path vs the row-split layout. Cell state
// c lives in lane-0 registers. Grid barrier tail VERBATIM R5 (passed 3x):
// store -> __syncthreads -> fence -> atomicAdd -> volatile spin -> fence ->
// __syncthreads. (bar.sync cumulativity + tid0's gpu-fence releases all
// warps' h-stores, exactly as in the proven version.)
__global__ __launch_bounds__(TPB, 1) void k_seq(const float* __restrict__ Whh,
                                                const float* __restrict__ G)
{
    const int b = blockIdx.x;
    const int tid = threadIdx.x;
    const int warp = tid >> 5, lane = tid & 31;

    __shared__ float hsh[HID];

    const int u = b * JPB + warp;    // hidden unit owned by this warp
    float creg = 0.f;                // cell state (lane 0 meaningful)

    int rows[4];
    float w[4][32];
    #pragma unroll
    for (int gate = 0; gate < 4; gate++) {
        rows[gate] = (gate << 10) + u;
        const float* wrow = Whh + (size_t)rows[gate] * HID + lane;
        #pragma unroll
        for (int i = 0; i < 32; i++) w[gate][i] = wrow[i * 32];
    }

    for (int t = 0; t < SEQ; t++) {
        // prefetch precomputed gate terms for this step (independent of h)
        float g0 = 0.f, g1 = 0.f, g2 = 0.f, g3 = 0.f;
        if (lane == 0) {
            const float* gt = G + (size_t)t * G4;
            g0 = __ldcg(gt + rows[0]);
            g1 = __ldcg(gt + rows[1]);
            g2 = __ldcg(gt + rows[2]);
            g3 = __ldcg(gt + rows[3]);
        }

        // load h (written by all blocks last step) — bypass L1
        const float* hg = g_st.h[t & 1];
        #pragma unroll
        for (int i = 0; i < HID / TPB; i++)
            hsh[tid + i * TPB] = __ldcg(hg + tid + i * TPB);
        __syncthreads();

        float hreg[32];
        #pragma unroll
        for (int i = 0; i < 32; i++) hreg[i] = hsh[i * 32 + lane];

        float a0 = 0.f, a1 = 0.f, a2 = 0.f, a3 = 0.f;
        #pragma unroll
        for (int i = 0; i < 32; i++) {
            a0 += w[0][i] * hreg[i];
            a1 += w[1][i] * hreg[i];
            a2 += w[2][i] * hreg[i];
            a3 += w[3][i] * hreg[i];
        }
        #pragma unroll
        for (int off = 16; off; off >>= 1) {
            a0 += __shfl_xor_sync(0xffffffffu, a0, off);
            a1 += __shfl_xor_sync(0xffffffffu, a1, off);
            a2 += __shfl_xor_sync(0xffffffffu, a2, off);
            a3 += __shfl_xor_sync(0xffffffffu, a3, off);
        }

        if (lane == 0) {
            float iv = a0 + g0;              // gate 0: input
            float fv = a1 + g1;              // gate 1: forget
            float gv = a2 + g2;              // gate 2: cell
            float ov = a3 + g3;              // gate 3: output
            float is = 1.f / (1.f + __expf(-iv));
            float fs = 1.f / (1.f + __expf(-fv));
            float os = 1.f / (1.f + __expf(-ov));
            float tg = 1.f - 2.f / (__expf(2.f * gv) + 1.f);   // tanh(gv)
            float cn = fs * creg + is * tg;
            creg = cn;
            float tc = 1.f - 2.f / (__expf(2.f * cn) + 1.f);   // tanh(cn)
            g_st.h[(t + 1) & 1][u] = os * tc;
        }
        __syncthreads();

        // grid barrier (release h-writes, acquire others') — VERBATIM R5
        if (tid == 0) {
            __threadfence();
            atomicAdd(&g_st.counter, 1u);
            unsigned target = (unsigned)(t + 1) * NB;
            while (*((volatile unsigned*)&g_st.counter) < target) { }
            __threadfence();
        }
        __syncthreads();
    }
}

// out[l] = dot(out_W[l], h_final) + out_b[l]; final h lives in buffer 0 (SEQ even)
__global__ void k_out(const float* __restrict__ outW, const float* __restrict__ outB,
                      float* __restrict__ out)
{
    int warp = threadIdx.x >> 5, lane = threadIdx.x & 31;
    if (warp < LABELS) {
        const float* wr = outW + (size_t)warp * HID;
        const float* h = g_st.h[0];
        float s = 0.f;
        for (int k = lane; k < HID; k += 32) s += wr[k] * h[k];
        #pragma unroll
        for (int off = 16; off; off >>= 1) s += __shfl_xor_sync(0xffffffffu, s, off);
        if (lane == 0) out[warp] = s + outB[warp];
    }
}

// ---------------- launch ----------------
// Order matters for profiling: ncu's capture empirically lands on app launch
// #4 -> prep(1), GEMM-C(2), GEMM-G(3), k_seq(4), k_out(5).
extern "C" void kernel_launch(void* const* d_in, const int* in_sizes, int n_in,
                              void* d_out, int out_size)
{
    const int*   sids  = (const int*)  d_in[0];
    const int*   eids  = (const int*)  d_in[1];
    const float* wemb  = (const float*)d_in[2];
    const float* eemb  = (const float*)d_in[3];
    // d_in[4] attn_W, d_in[5] attn_b: mathematically dead (softmax of 1 logit == 1)
    const float* combW = (const float*)d_in[6];
    const float* combB = (const float*)d_in[7];
    const float* Wih   = (const float*)d_in[8];
    const float* Whh   = (const float*)d_in[9];
    const float* bih   = (const float*)d_in[10];
    const float* bhh   = (const float*)d_in[11];
    const float* outW  = (const float*)d_in[12];
    const float* outB  = (const float*)d_in[13];
    float* out = (float*)d_out;

    void *pC = 0, *pG = 0, *pc2 = 0;
    cudaGetSymbolAddress(&pC,  g_C);
    cudaGetSymbolAddress(&pG,  g_G);
    cudaGetSymbolAddress(&pc2, g_const2);

    k_prep<<<NB, TPB>>>(eids, eemb, combW, combB);

    // C = relu(gather(word_emb, sids) @ Wx^T + const2), Wx = comb_W[:, 0:EMB]
    dim3 gridC(EMB / 128, SEQ / 128);
    sgemm_nt<<<gridC, 256>>>(wemb, EMB, sids, combW, 2 * EMB,
                             (const float*)pc2, (const float*)0,
                             (float*)pC, EMB, EMB, 1);

    // G = C @ W_ih^T + b_ih + b_hh   (both biases folded into epilogue)
    dim3 gridG(G4 / 128, SEQ / 128);
    sgemm_nt<<<gridG, 256>>>((const float*)pC, EMB, (const int*)0, Wih, EMB,
                             bih, bhh, (float*)pG, G4, EMB, 0);

    k_seq<<<NB, TPB>>>(Whh, (const float*)pG);
    k_out<<<1, 256>>>(outW, outB, out);
}